// round 2
// baseline (speedup 1.0000x reference)
#include <cuda_runtime.h>
#include <cstdint>

// S4 kernel materialization:
//   K[h,l] = 2 * Re( sum_n Cc[h,n] * exp(dtA[h,n])^l ),  Cc = C * (exp(dtA)-1)/A
// Factor l = 64*q + r  ->  per-h 64x64x64 real GEMM, inner loop on packed
// fp32x2 FMA (SASS FFMA2) for 2x fp32 pipe throughput on sm_103a.

#define Hh   1024
#define NHn  32
#define Ll   4096

__global__ __launch_bounds__(256, 4)
void s4_vandermonde_gemm(const float* __restrict__ Cin,        // [H, NH, 2]
                         const float* __restrict__ log_dt,     // [H]
                         const float* __restrict__ log_A_real, // [H, NH]
                         const float* __restrict__ A_imag,     // [H, NH]
                         float* __restrict__ out)              // [H, L]
{
    __shared__ float Ash[64][64];   // Ash[j][q] : j = 2n(+1), q-major rows
    __shared__ float Bsh[64][64];   // Bsh[j][r]
    __shared__ float s_dtar[NHn], s_dtai[NHn], s_cr[NHn], s_ci[NHn];

    const int h   = blockIdx.x;
    const int tid = threadIdx.x;

    // ---- per-n parameters (32 threads) ----
    if (tid < NHn) {
        int n = tid;
        float dt   = expf(log_dt[h]);
        float Are  = -expf(log_A_real[h * NHn + n]);   // Re(A)
        float Aim  = -A_imag[h * NHn + n];             // Im(A)
        float dtar = Are * dt;
        float dtai = Aim * dt;

        // e = exp(dtA)
        float er = expf(dtar);
        float sn, cs;
        sincosf(dtai, &sn, &cs);
        float e_re = er * cs;
        float e_im = er * sn;

        // f = (e - 1) / A = (e-1) * conj(A) / |A|^2
        float num_re = e_re - 1.0f;
        float num_im = e_im;
        float inv    = 1.0f / (Are * Are + Aim * Aim);
        float f_re   = (num_re * Are + num_im * Aim) * inv;
        float f_im   = (num_im * Are - num_re * Aim) * inv;

        // Cc = (C0 + i C1) * f
        float c0 = Cin[(h * NHn + n) * 2 + 0];
        float c1 = Cin[(h * NHn + n) * 2 + 1];
        s_cr[n]   = c0 * f_re - c1 * f_im;
        s_ci[n]   = c0 * f_im + c1 * f_re;
        s_dtar[n] = dtar;
        s_dtai[n] = dtai;
    }
    __syncthreads();

    // ---- build tables: A (z^{64q}) and B (2*Cc*z^r with sign fold) ----
    #pragma unroll
    for (int k = 0; k < 8; k++) {
        int idx = tid + k * 256;
        int n   = idx >> 6;
        int q   = idx & 63;
        float dtar = s_dtar[n];
        float dtai = s_dtai[n];

        float tq  = 64.0f * (float)q;
        float mag = expf(dtar * tq);
        float sq, cq;
        sincosf(dtai * tq, &sq, &cq);
        Ash[2 * n    ][q] = mag * cq;
        Ash[2 * n + 1][q] = mag * sq;

        float tr   = (float)q;
        float magr = expf(dtar * tr);
        float sr, cr;
        sincosf(dtai * tr, &sr, &cr);
        float pr = magr * cr;
        float pi = magr * sr;
        float ccr = s_cr[n];
        float cci = s_ci[n];
        Bsh[2 * n    ][q] =  2.0f * (ccr * pr - cci * pi);
        Bsh[2 * n + 1][q] = -2.0f * (ccr * pi + cci * pr);
    }
    __syncthreads();

    // ---- 64x64x64 GEMM on packed f32x2 ----
    // thread (tx,ty): 4x4 tile at (q = 4*ty .., r = 4*tx ..)
    // accumulators packed along q: acc[p][r] = (K[qb+2p][r], K[qb+2p+1][r])
    const int tx = tid & 15;
    const int ty = tid >> 4;
    const int rb = tx * 4;
    const int qb = ty * 4;

    unsigned long long acc[2][4];
    #pragma unroll
    for (int p = 0; p < 2; p++)
        #pragma unroll
        for (int r = 0; r < 4; r++)
            acc[p][r] = 0ULL;

    #pragma unroll 16
    for (int j = 0; j < 64; j++) {
        // packed (A[j][qb], A[j][qb+1]) and (A[j][qb+2], A[j][qb+3])
        unsigned long long a0 = *(const unsigned long long*)&Ash[j][qb];
        unsigned long long a1 = *(const unsigned long long*)&Ash[j][qb + 2];
        float4 b = *(const float4*)&Bsh[j][rb];

        unsigned long long b0, b1, b2, b3;
        asm("mov.b64 %0, {%1, %1};" : "=l"(b0) : "f"(b.x));
        asm("mov.b64 %0, {%1, %1};" : "=l"(b1) : "f"(b.y));
        asm("mov.b64 %0, {%1, %1};" : "=l"(b2) : "f"(b.z));
        asm("mov.b64 %0, {%1, %1};" : "=l"(b3) : "f"(b.w));

        asm("fma.rn.f32x2 %0, %1, %2, %0;" : "+l"(acc[0][0]) : "l"(a0), "l"(b0));
        asm("fma.rn.f32x2 %0, %1, %2, %0;" : "+l"(acc[0][1]) : "l"(a0), "l"(b1));
        asm("fma.rn.f32x2 %0, %1, %2, %0;" : "+l"(acc[0][2]) : "l"(a0), "l"(b2));
        asm("fma.rn.f32x2 %0, %1, %2, %0;" : "+l"(acc[0][3]) : "l"(a0), "l"(b3));
        asm("fma.rn.f32x2 %0, %1, %2, %0;" : "+l"(acc[1][0]) : "l"(a1), "l"(b0));
        asm("fma.rn.f32x2 %0, %1, %2, %0;" : "+l"(acc[1][1]) : "l"(a1), "l"(b1));
        asm("fma.rn.f32x2 %0, %1, %2, %0;" : "+l"(acc[1][2]) : "l"(a1), "l"(b2));
        asm("fma.rn.f32x2 %0, %1, %2, %0;" : "+l"(acc[1][3]) : "l"(a1), "l"(b3));
    }

    // ---- store: out[h, 64*q + r], unpack q-pairs ----
    float* o = out + (size_t)h * Ll;
    float2 u00 = *(float2*)&acc[0][0];
    float2 u01 = *(float2*)&acc[0][1];
    float2 u02 = *(float2*)&acc[0][2];
    float2 u03 = *(float2*)&acc[0][3];
    float2 u10 = *(float2*)&acc[1][0];
    float2 u11 = *(float2*)&acc[1][1];
    float2 u12 = *(float2*)&acc[1][2];
    float2 u13 = *(float2*)&acc[1][3];

    float4 v0 = make_float4(u00.x, u01.x, u02.x, u03.x);  // row qb+0
    float4 v1 = make_float4(u00.y, u01.y, u02.y, u03.y);  // row qb+1
    float4 v2 = make_float4(u10.x, u11.x, u12.x, u13.x);  // row qb+2
    float4 v3 = make_float4(u10.y, u11.y, u12.y, u13.y);  // row qb+3

    *(float4*)&o[(qb + 0) * 64 + rb] = v0;
    *(float4*)&o[(qb + 1) * 64 + rb] = v1;
    *(float4*)&o[(qb + 2) * 64 + rb] = v2;
    *(float4*)&o[(qb + 3) * 64 + rb] = v3;
}

extern "C" void kernel_launch(void* const* d_in, const int* in_sizes, int n_in,
                              void* d_out, int out_size)
{
    const float* C          = (const float*)d_in[0];   // [H, NH, 2]
    const float* log_dt     = (const float*)d_in[1];   // [H]
    const float* log_A_real = (const float*)d_in[2];   // [H, NH]
    const float* A_imag     = (const float*)d_in[3];   // [H, NH]
    float* out              = (float*)d_out;           // [H, L]

    s4_vandermonde_gemm<<<Hh, 256>>>(C, log_dt, log_A_real, A_imag, out);
}

// round 3
// speedup vs baseline: 1.0514x; 1.0514x over previous
#include <cuda_runtime.h>

// S4 kernel materialization:
//   K[h,l] = 2 * Re( sum_n Cc[h,n] * exp(dtA[h,n])^l ),  Cc = C * (exp(dtA)-1)/A
// Factor l = 64*q + r  ->  per-h 64x64x64 real GEMM.
// R3: occupancy fix — force 6 CTAs/SM (reg cap 42) to hide LDS/FFMA latency.

#define Hh   1024
#define NHn  32
#define Ll   4096

__global__ __launch_bounds__(256, 6)
void s4_vandermonde_gemm(const float* __restrict__ Cin,        // [H, NH, 2]
                         const float* __restrict__ log_dt,     // [H]
                         const float* __restrict__ log_A_real, // [H, NH]
                         const float* __restrict__ A_imag,     // [H, NH]
                         float* __restrict__ out)              // [H, L]
{
    __shared__ float Ash[64][64];   // Ash[j][q]
    __shared__ float Bsh[64][64];   // Bsh[j][r]
    __shared__ float s_dtar[NHn], s_dtai[NHn], s_cr[NHn], s_ci[NHn];

    const int h   = blockIdx.x;
    const int tid = threadIdx.x;

    // ---- per-n parameters (32 threads) ----
    if (tid < NHn) {
        int n = tid;
        float dt   = expf(log_dt[h]);
        float Are  = -expf(log_A_real[h * NHn + n]);   // Re(A)
        float Aim  = -A_imag[h * NHn + n];             // Im(A)
        float dtar = Are * dt;
        float dtai = Aim * dt;

        // e = exp(dtA)
        float er = expf(dtar);
        float sn, cs;
        sincosf(dtai, &sn, &cs);
        float e_re = er * cs;
        float e_im = er * sn;

        // f = (e - 1) / A = (e-1) * conj(A) / |A|^2
        float num_re = e_re - 1.0f;
        float num_im = e_im;
        float inv    = 1.0f / (Are * Are + Aim * Aim);
        float f_re   = (num_re * Are + num_im * Aim) * inv;
        float f_im   = (num_im * Are - num_re * Aim) * inv;

        // Cc = (C0 + i C1) * f
        float c0 = Cin[(h * NHn + n) * 2 + 0];
        float c1 = Cin[(h * NHn + n) * 2 + 1];
        s_cr[n]   = c0 * f_re - c1 * f_im;
        s_ci[n]   = c0 * f_im + c1 * f_re;
        s_dtar[n] = dtar;
        s_dtai[n] = dtai;
    }
    __syncthreads();

    // ---- build tables: A (z^{64q}) and B (2*Cc*z^r with sign fold) ----
    // NH*64 = 2048 (n, idx) pairs, 256 threads -> 8 each
    #pragma unroll
    for (int k = 0; k < 8; k++) {
        int idx = tid + k * 256;
        int n   = idx >> 6;
        int q   = idx & 63;
        float dtar = s_dtar[n];
        float dtai = s_dtai[n];

        // Q = exp(dtA * 64q)
        float tq  = 64.0f * (float)q;
        float mag = expf(dtar * tq);
        float sq, cq;
        sincosf(dtai * tq, &sq, &cq);
        Ash[2 * n    ][q] = mag * cq;
        Ash[2 * n + 1][q] = mag * sq;

        // P = Cc * exp(dtA * r)
        float tr   = (float)q;
        float magr = expf(dtar * tr);
        float sr, cr;
        sincosf(dtai * tr, &sr, &cr);
        float pr = magr * cr;
        float pi = magr * sr;
        float ccr = s_cr[n];
        float cci = s_ci[n];
        Bsh[2 * n    ][q] =  2.0f * (ccr * pr - cci * pi);
        Bsh[2 * n + 1][q] = -2.0f * (ccr * pi + cci * pr);
    }
    __syncthreads();

    // ---- 64x64x64 GEMM: thread (tx,ty) computes 4x4 tile at (q=4ty.., r=4tx..) ----
    const int tx = tid & 15;
    const int ty = tid >> 4;
    const int rb = tx * 4;
    const int qb = ty * 4;

    float acc00 = 0.f, acc01 = 0.f, acc02 = 0.f, acc03 = 0.f;
    float acc10 = 0.f, acc11 = 0.f, acc12 = 0.f, acc13 = 0.f;
    float acc20 = 0.f, acc21 = 0.f, acc22 = 0.f, acc23 = 0.f;
    float acc30 = 0.f, acc31 = 0.f, acc32 = 0.f, acc33 = 0.f;

    #pragma unroll 8
    for (int j = 0; j < 64; j++) {
        float4 a = *(const float4*)&Ash[j][qb];
        float4 b = *(const float4*)&Bsh[j][rb];
        acc00 = fmaf(a.x, b.x, acc00);
        acc01 = fmaf(a.x, b.y, acc01);
        acc02 = fmaf(a.x, b.z, acc02);
        acc03 = fmaf(a.x, b.w, acc03);
        acc10 = fmaf(a.y, b.x, acc10);
        acc11 = fmaf(a.y, b.y, acc11);
        acc12 = fmaf(a.y, b.z, acc12);
        acc13 = fmaf(a.y, b.w, acc13);
        acc20 = fmaf(a.z, b.x, acc20);
        acc21 = fmaf(a.z, b.y, acc21);
        acc22 = fmaf(a.z, b.z, acc22);
        acc23 = fmaf(a.z, b.w, acc23);
        acc30 = fmaf(a.w, b.x, acc30);
        acc31 = fmaf(a.w, b.y, acc31);
        acc32 = fmaf(a.w, b.z, acc32);
        acc33 = fmaf(a.w, b.w, acc33);
    }

    // ---- store: out[h, 64*q + r] ----
    float* o = out + (size_t)h * Ll;
    float4 v0 = make_float4(acc00, acc01, acc02, acc03);
    float4 v1 = make_float4(acc10, acc11, acc12, acc13);
    float4 v2 = make_float4(acc20, acc21, acc22, acc23);
    float4 v3 = make_float4(acc30, acc31, acc32, acc33);
    *(float4*)&o[(qb + 0) * 64 + rb] = v0;
    *(float4*)&o[(qb + 1) * 64 + rb] = v1;
    *(float4*)&o[(qb + 2) * 64 + rb] = v2;
    *(float4*)&o[(qb + 3) * 64 + rb] = v3;
}

extern "C" void kernel_launch(void* const* d_in, const int* in_sizes, int n_in,
                              void* d_out, int out_size)
{
    const float* C          = (const float*)d_in[0];   // [H, NH, 2]
    const float* log_dt     = (const float*)d_in[1];   // [H]
    const float* log_A_real = (const float*)d_in[2];   // [H, NH]
    const float* A_imag     = (const float*)d_in[3];   // [H, NH]
    float* out              = (float*)d_out;           // [H, L]

    s4_vandermonde_gemm<<<Hh, 256>>>(C, log_dt, log_A_real, A_imag, out);
}

// round 5
// speedup vs baseline: 1.6106x; 1.5319x over previous
#include <cuda_runtime.h>
#include <cuda_bf16.h>
#include <cstdint>

// S4 kernel materialization on the tensor pipe (baseline mma.sync HMMA):
//   K[h,l] = 2*Re( sum_n Cc_n z_n^l ),  z = exp(dtA), Cc = C*(z-1)/A
// Split l = 64q + r  ->  per-h real GEMM  D[64q][64r] = A[64x64] @ B[64x64]
//   A[q][2n]=Re z^(64q), A[q][2n+1]=Im z^(64q)
//   B[2n][r]=2Re(Cc z^r), B[2n+1][r]=-2Im(Cc z^r)   (stored col-major = B^T[r][j])
// bf16 hi/lo 3-product split: D = Ahi*Bhi + Ahi*Blo + Alo*Bhi, fp32 accum.

#define Hh   1024
#define NHn  32
#define Ll   4096

__device__ __forceinline__ uint32_t split_pack(float re, float im, uint32_t& lo_out) {
    __nv_bfloat16 hr = __float2bfloat16_rn(re);
    __nv_bfloat16 hm = __float2bfloat16_rn(im);
    float lr = re - __bfloat162float(hr);
    float lm = im - __bfloat162float(hm);
    __nv_bfloat16 lr16 = __float2bfloat16_rn(lr);
    __nv_bfloat16 lm16 = __float2bfloat16_rn(lm);
    lo_out = ((uint32_t)__bfloat16_as_ushort(lm16) << 16) | __bfloat16_as_ushort(lr16);
    return  ((uint32_t)__bfloat16_as_ushort(hm)   << 16) | __bfloat16_as_ushort(hr);
}

__device__ __forceinline__ void mma16816(float* c, const uint32_t* a,
                                         uint32_t b0, uint32_t b1) {
    asm volatile(
        "mma.sync.aligned.m16n8k16.row.col.f32.bf16.bf16.f32 "
        "{%0,%1,%2,%3}, {%4,%5,%6,%7}, {%8,%9}, {%0,%1,%2,%3};"
        : "+f"(c[0]), "+f"(c[1]), "+f"(c[2]), "+f"(c[3])
        : "r"(a[0]), "r"(a[1]), "r"(a[2]), "r"(a[3]), "r"(b0), "r"(b1));
}

__global__ __launch_bounds__(128)
void s4_hmma_kernel(const float* __restrict__ Cin,        // [H, NH, 2]
                    const float* __restrict__ log_dt,     // [H]
                    const float* __restrict__ log_A_real, // [H, NH]
                    const float* __restrict__ A_imag,     // [H, NH]
                    float* __restrict__ out)              // [H, L]
{
    // 64 rows x 32 words (64 bf16) per tile, XOR-swizzled: word = col ^ ((row&7)<<2)
    __shared__ uint32_t Ahi[64 * 32], Alo[64 * 32];
    __shared__ uint32_t Bhi[64 * 32], Blo[64 * 32];
    // anchors: [idx][n] as float2
    __shared__ float2 s_wa[8 * 32], s_wb[8 * 32];   // A: z^(512a), z^(64b)
    __shared__ float2 s_va[8 * 32], s_vb[8 * 32];   // B: Cc*z^(8a), z^b

    const int h    = blockIdx.x;
    const int tid  = threadIdx.x;
    const int lane = tid & 31;
    const int w    = tid >> 5;

    // ---- phase 1: per-n params + anchor chains (warp 0 only) ----
    if (tid < NHn) {
        int n = tid;
        float dt   = expf(log_dt[h]);
        float Are  = -expf(log_A_real[h * NHn + n]);
        float Aim  = -A_imag[h * NHn + n];
        float dtar = Are * dt;
        float dtai = Aim * dt;

        float er = expf(dtar);
        float sn, cs;
        sincosf(dtai, &sn, &cs);
        float zr = er * cs, zi = er * sn;            // z = exp(dtA)

        // Cc = C * (z-1)/A
        float nr = zr - 1.0f, ni = zi;
        float inv = 1.0f / (Are * Are + Aim * Aim);
        float fr = (nr * Are + ni * Aim) * inv;
        float fi = (ni * Are - nr * Aim) * inv;
        float c0 = Cin[(h * NHn + n) * 2 + 0];
        float c1 = Cin[(h * NHn + n) * 2 + 1];
        float ccr = c0 * fr - c1 * fi;
        float cci = c0 * fi + c1 * fr;

        // vb[b] = z^b (b<8)
        float pr = 1.0f, pi = 0.0f;
        #pragma unroll
        for (int b = 0; b < 8; b++) {
            s_vb[b * 32 + n] = make_float2(pr, pi);
            float t = pr * zr - pi * zi; pi = pr * zi + pi * zr; pr = t;
        }
        // z8 = z^8 (3 squarings)
        float ar = zr, ai = zi;
        #pragma unroll
        for (int s = 0; s < 3; s++) { float t = ar*ar - ai*ai; ai = 2.0f*ar*ai; ar = t; }
        float z8r = ar, z8i = ai;
        // va[a] = Cc * z^(8a) (a<8)
        pr = ccr; pi = cci;
        #pragma unroll
        for (int a = 0; a < 8; a++) {
            s_va[a * 32 + n] = make_float2(pr, pi);
            float t = pr * z8r - pi * z8i; pi = pr * z8i + pi * z8r; pr = t;
        }
        // z64 = z8^8 (3 squarings)
        #pragma unroll
        for (int s = 0; s < 3; s++) { float t = ar*ar - ai*ai; ai = 2.0f*ar*ai; ar = t; }
        float z64r = ar, z64i = ai;
        // wb[b] = z^(64b)
        pr = 1.0f; pi = 0.0f;
        #pragma unroll
        for (int b = 0; b < 8; b++) {
            s_wb[b * 32 + n] = make_float2(pr, pi);
            float t = pr * z64r - pi * z64i; pi = pr * z64i + pi * z64r; pr = t;
        }
        // z512 = z64^8 (3 squarings)
        #pragma unroll
        for (int s = 0; s < 3; s++) { float t = ar*ar - ai*ai; ai = 2.0f*ar*ai; ar = t; }
        float z512r = ar, z512i = ai;
        // wa[a] = z^(512a)
        pr = 1.0f; pi = 0.0f;
        #pragma unroll
        for (int a = 0; a < 8; a++) {
            s_wa[a * 32 + n] = make_float2(pr, pi);
            float t = pr * z512r - pi * z512i; pi = pr * z512i + pi * z512r; pr = t;
        }
    }
    __syncthreads();

    // ---- phase 2: build bf16 hi/lo tiles (all 128 threads) ----
    {
        int n = lane;
        #pragma unroll
        for (int kk = 0; kk < 16; kk++) {
            int row = kk * 4 + w;                  // row = q (A) / r (B)
            int wo  = row * 32 + (n ^ ((row & 7) << 2));
            // A[q]: z^(64q) = wa[q>>3] * wb[q&7]
            float2 a1 = s_wa[(row >> 3) * 32 + n];
            float2 a2 = s_wb[(row & 7) * 32 + n];
            float  vr = a1.x * a2.x - a1.y * a2.y;
            float  vi = a1.x * a2.y + a1.y * a2.x;
            uint32_t lo, hi = split_pack(vr, vi, lo);
            Ahi[wo] = hi; Alo[wo] = lo;
            // B[r]: Cc z^r = va[r>>3] * vb[r&7], fold (2, -2)
            float2 b1 = s_va[(row >> 3) * 32 + n];
            float2 b2 = s_vb[(row & 7) * 32 + n];
            float  ur = b1.x * b2.x - b1.y * b2.y;
            float  ui = b1.x * b2.y + b1.y * b2.x;
            hi = split_pack(2.0f * ur, -2.0f * ui, lo);
            Bhi[wo] = hi; Blo[wo] = lo;
        }
    }
    __syncthreads();

    // ---- phase 3: MMA. warp w owns q rows [16w, 16w+16) ----
    const int lane4 = lane >> 2;          // 0..7
    const int kq    = lane & 3;           // 0..3
    const int xr    = lane4 << 2;         // word-XOR (row&7 == lane4 for all rows used)
    const int rowA0 = w * 16 + lane4;

    float acc[8][4];
    #pragma unroll
    for (int nt = 0; nt < 8; nt++)
        #pragma unroll
        for (int i = 0; i < 4; i++) acc[nt][i] = 0.0f;

    #pragma unroll
    for (int ks = 0; ks < 4; ks++) {
        int wc0 = ks * 8 + kq;            // word col of k element pair
        int wc1 = wc0 + 4;                // +8 k elements
        int o00 = rowA0 * 32 + (wc0 ^ xr);
        int o10 = (rowA0 + 8) * 32 + (wc0 ^ xr);
        int o01 = rowA0 * 32 + (wc1 ^ xr);
        int o11 = (rowA0 + 8) * 32 + (wc1 ^ xr);
        uint32_t ah[4] = { Ahi[o00], Ahi[o10], Ahi[o01], Ahi[o11] };
        uint32_t al[4] = { Alo[o00], Alo[o10], Alo[o01], Alo[o11] };

        #pragma unroll
        for (int nt = 0; nt < 8; nt++) {
            int rowB = nt * 8 + lane4;
            int ob0  = rowB * 32 + (wc0 ^ xr);
            int ob1  = rowB * 32 + (wc1 ^ xr);
            uint32_t bh0 = Bhi[ob0], bh1 = Bhi[ob1];
            uint32_t bl0 = Blo[ob0], bl1 = Blo[ob1];
            mma16816(acc[nt], ah, bh0, bh1);
            mma16816(acc[nt], ah, bl0, bl1);
            mma16816(acc[nt], al, bh0, bh1);
        }
    }

    // ---- epilogue: D(q, r) -> out[h, 64q + r] ----
    float* o = out + (size_t)h * Ll;
    const int q0 = rowA0, q1 = rowA0 + 8;
    const int cb = kq * 2;
    #pragma unroll
    for (int nt = 0; nt < 8; nt++) {
        int c = nt * 8 + cb;
        *(float2*)&o[q0 * 64 + c] = make_float2(acc[nt][0], acc[nt][1]);
        *(float2*)&o[q1 * 64 + c] = make_float2(acc[nt][2], acc[nt][3]);
    }
}

extern "C" void kernel_launch(void* const* d_in, const int* in_sizes, int n_in,
                              void* d_out, int out_size)
{
    const float* C          = (const float*)d_in[0];   // [H, NH, 2]
    const float* log_dt     = (const float*)d_in[1];   // [H]
    const float* log_A_real = (const float*)d_in[2];   // [H, NH]
    const float* A_imag     = (const float*)d_in[3];   // [H, NH]
    float* out              = (float*)d_out;           // [H, L]

    s4_hmma_kernel<<<Hh, 128>>>(C, log_dt, log_A_real, A_imag, out);
}